// round 16
// baseline (speedup 1.0000x reference)
#include <cuda_runtime.h>
#include <cuda_fp16.h>

#define HH   256
#define P5   1024
#define NQ   128
#define GRID_MAIN  152   // GB300 SM count
#define BLOCK_MAIN 768   // 24 warps/SM = 6/SMSP (proven necessary); 1 pt/thread

__device__ float g_w2r[HH];
__device__ float g_c;

__device__ __forceinline__ float warp_sum(float v) {
    #pragma unroll
    for (int o = 16; o; o >>= 1) v += __shfl_xor_sync(0xffffffffu, v, o);
    return v;
}

// bit-cast helpers (no SASS cost)
__device__ __forceinline__ unsigned h2_to_u(__half2 h) {
    return *reinterpret_cast<unsigned*>(&h);
}
__device__ __forceinline__ __half2 u_to_h2(unsigned u) {
    return *reinterpret_cast<__half2*>(&u);
}

// tanh.approx.f16x2 on an already-packed half2 (as raw b32). ONE XU op.
__device__ __forceinline__ unsigned tanh2_h2(unsigned z2) {
    unsigned t;
    asm("tanh.approx.f16x2 %0, %1;" : "=r"(t) : "r"(z2));
    return t;
}

// ---------------------------------------------------------------------------
// Kernel 1 (fused setup + w2r): 128 blocks x 256 threads. (unchanged, proven)
// ---------------------------------------------------------------------------
__global__ __launch_bounds__(256)
void w2r_fused_kernel(
    const float* __restrict__ eq,
    const float* __restrict__ q0, const float* __restrict__ q1,
    const float* __restrict__ q2, const float* __restrict__ q3,
    const float* __restrict__ q4,
    const float* __restrict__ Wq0, const float* __restrict__ bq0,
    const float* __restrict__ Wq1, const float* __restrict__ bq1,
    const float* __restrict__ Wq2, const float* __restrict__ bq2,
    const float* __restrict__ Wq3, const float* __restrict__ bq3,
    const float* __restrict__ Wq4, const float* __restrict__ bq4,
    const float* __restrict__ bx2,
    const float* __restrict__ Wx2)
{
    __shared__ float s[5][64];
    __shared__ float t01[16][16];
    __shared__ float t23[16][16];
    __shared__ float partA[5][4], partB[5][4];
    __shared__ float sA[5], sB[5];
    __shared__ float red[8];

    const int tid  = threadIdx.x;
    const int lane = tid & 31;
    const int wrp  = tid >> 5;
    const int h0   = blockIdx.x * 2;

    const float4 wrow0 = reinterpret_cast<const float4*>(Wx2 + h0 * P5)[tid];
    const float4 wrow1 = reinterpret_cast<const float4*>(Wx2 + (h0 + 1) * P5)[tid];

    const float eqv = eq[0];

    if (tid < NQ) {
        const float* qp[5] = {q0, q1, q2, q3, q4};
        #pragma unroll
        for (int i = 0; i < 5; i++) {
            float q = qp[i][tid];
            float y = __expf(-q * q * eqv);
            float a = warp_sum(y * q);
            float b = warp_sum(y);
            if (lane == 0) { partA[i][wrp] = a; partB[i][wrp] = b; }
        }
    }
    __syncthreads();
    if (tid < 5) {
        sA[tid] = partA[tid][0] + partA[tid][1] + partA[tid][2] + partA[tid][3];
        sB[tid] = partB[tid][0] + partB[tid][1] + partB[tid][2] + partB[tid][3];
    }
    __syncthreads();

    if (tid < 64) {
        s[0][tid] = sA[0] * Wq0[tid] + sB[0] * bq0[tid];
        s[1][tid] = sA[1] * Wq1[tid] + sB[1] * bq1[tid];
        s[2][tid] = sA[2] * Wq2[tid] + sB[2] * bq2[tid];
        s[3][tid] = sA[3] * Wq3[tid] + sB[3] * bq3[tid];
        s[4][tid] = sA[4] * Wq4[tid] + sB[4] * bq4[tid];
    }
    __syncthreads();

    {
        int pq = tid >> 4;
        int x  = tid & 15;
        t01[x][pq] = s[0][(pq >> 2) * 16 + x] * s[1][(pq & 3) * 16 + x];
        t23[x][pq] = s[2][(pq >> 2) * 16 + x] * s[3][(pq & 3) * 16 + x];
    }
    __syncthreads();

    const int bd = tid >> 4;
    const int fm = tid & 15;
    float a0 = 0.f, a1 = 0.f, a2 = 0.f, a3 = 0.f;
    #pragma unroll
    for (int x = 0; x < 16; x++) {
        float u = t01[x][bd] * t23[x][fm];
        a0 = fmaf(u, s[4][x],      a0);
        a1 = fmaf(u, s[4][16 + x], a1);
        a2 = fmaf(u, s[4][32 + x], a2);
        a3 = fmaf(u, s[4][48 + x], a3);
    }

    float d0 = wrow0.x * a0 + wrow0.y * a1 + wrow0.z * a2 + wrow0.w * a3;
    float d1 = wrow1.x * a0 + wrow1.y * a1 + wrow1.z * a2 + wrow1.w * a3;
    d0 = warp_sum(d0);
    d1 = warp_sum(d1);
    if (lane == 0) red[wrp] = d0;
    __syncthreads();
    if (tid == 0) {
        float t = 0.f;
        #pragma unroll
        for (int w = 0; w < 8; w++) t += red[w];
        g_w2r[h0] = t;
    }
    __syncthreads();
    if (lane == 0) red[wrp] = d1;
    __syncthreads();
    if (tid == 0) {
        float t = 0.f;
        #pragma unroll
        for (int w = 0; w < 8; w++) t += red[w];
        g_w2r[h0 + 1] = t;
    }

    if (blockIdx.x == 0) {
        float4 bv = reinterpret_cast<const float4*>(bx2)[tid];
        float cp = a0 * bv.x + a1 * bv.y + a2 * bv.z + a3 * bv.w;
        cp = warp_sum(cp);
        __syncthreads();
        if (lane == 0) red[wrp] = cp;
        __syncthreads();
        if (tid == 0) {
            float c = 0.f;
            #pragma unroll
            for (int w = 0; w < 8; w++) c += red[w];
            g_c = c;
        }
    }
}

// ---------------------------------------------------------------------------
// Kernel 2: out[n] = c + sum_h tanh(z_h(n)) * w2r[h].
// h in QUADS (two f16x2 pairs per iter): weights half2-packed in smem,
// z = 3 HFMA2 per pair, tanh.approx.f16x2 consumes z directly (no pack cvt),
// exact ALU bit-surgery unpack (as_float(sign|mag<<13) == tanh * 2^-112),
// f32 scaled-domain accumulate, one epilogue FMA applies 2^112 + c.
// Quad tiling amortizes LDS/loop overhead: ~27 insts per 4 tanh-evals.
// ---------------------------------------------------------------------------
__global__ __launch_bounds__(BLOCK_MAIN)
void main_kernel(const float* __restrict__ input,
                 const float* __restrict__ Wx1,
                 const float* __restrict__ bx1,
                 float* __restrict__ out, int N)
{
    __shared__ uint4  sWa[HH / 4];   // {wx2,wy2,wz2,b2} for pair (4q, 4q+1)
    __shared__ uint4  sWb[HH / 4];   // {wx2,wy2,wz2,b2} for pair (4q+2, 4q+3)
    __shared__ float4 sR4[HH / 4];   // {w2r[4q..4q+3]}
    __shared__ float  sC;
    const int tid = threadIdx.x;
    if (tid < HH / 2) {
        const int j = 2 * tid;                    // h-pair start (even h)
        __half2 wx2 = __floats2half2_rn(Wx1[j],          Wx1[j + 1]);
        __half2 wy2 = __floats2half2_rn(Wx1[HH + j],     Wx1[HH + j + 1]);
        __half2 wz2 = __floats2half2_rn(Wx1[2 * HH + j], Wx1[2 * HH + j + 1]);
        __half2 b2  = __floats2half2_rn(bx1[j],          bx1[j + 1]);
        uint4 w;
        w.x = h2_to_u(wx2); w.y = h2_to_u(wy2);
        w.z = h2_to_u(wz2); w.w = h2_to_u(b2);
        if (tid & 1) sWb[tid >> 1] = w; else sWa[tid >> 1] = w;
    }
    if (tid < HH / 4) {
        const int j = 4 * tid;
        sR4[tid] = make_float4(g_w2r[j], g_w2r[j + 1], g_w2r[j + 2], g_w2r[j + 3]);
    }
    if (tid == 0) sC = g_c;
    __syncthreads();

    const int ppb  = (N + GRID_MAIN - 1) / GRID_MAIN;   // 658 for N=100000
    const int base = blockIdx.x * ppb;
    const int end  = min(base + ppb, N);
    const float c  = sC;

    for (int n0 = base; n0 < end; n0 += BLOCK_MAIN) {
        const int  n = n0 + tid;
        const bool v = n < end;
        float x0 = 0.f, x1 = 0.f, x2 = 0.f;
        if (v) { x0 = input[3 * n]; x1 = input[3 * n + 1]; x2 = input[3 * n + 2]; }

        const __half2 x0d = __float2half2_rn(x0);   // {x0, x0}
        const __half2 x1d = __float2half2_rn(x1);
        const __half2 x2d = __float2half2_rn(x2);

        float acc = 0.f;                 // scaled domain (x 2^-112)
        #pragma unroll 8
        for (int q = 0; q < HH / 4; q++) {
            uint4  wa = sWa[q];          // pair (4q, 4q+1)
            uint4  wb = sWb[q];          // pair (4q+2, 4q+3)
            float4 r4 = sR4[q];

            __half2 za = __hfma2(x0d, u_to_h2(wa.x),
                         __hfma2(x1d, u_to_h2(wa.y),
                         __hfma2(x2d, u_to_h2(wa.z), u_to_h2(wa.w))));
            __half2 zb = __hfma2(x0d, u_to_h2(wb.x),
                         __hfma2(x1d, u_to_h2(wb.y),
                         __hfma2(x2d, u_to_h2(wb.z), u_to_h2(wb.w))));

            unsigned ta = tanh2_h2(h2_to_u(za));    // {tanh(h4q), tanh(h4q+1)}
            unsigned tb = tanh2_h2(h2_to_u(zb));    // {tanh(h4q+2), tanh(h4q+3)}

            // exact f16 -> (tanh * 2^-112) as f32, pure ALU
            unsigned lo0 = ((ta << 16) & 0x80000000u) | ((ta & 0x7FFFu) << 13);
            unsigned hi0 = (ta & 0x80000000u) | ((ta >> 3) & 0x0FFFE000u);
            unsigned lo1 = ((tb << 16) & 0x80000000u) | ((tb & 0x7FFFu) << 13);
            unsigned hi1 = (tb & 0x80000000u) | ((tb >> 3) & 0x0FFFE000u);

            acc = fmaf(__uint_as_float(lo0), r4.x, acc);
            acc = fmaf(__uint_as_float(hi0), r4.y, acc);
            acc = fmaf(__uint_as_float(lo1), r4.z, acc);
            acc = fmaf(__uint_as_float(hi1), r4.w, acc);
        }
        if (v) out[n] = fmaf(acc, 0x1p+112f, c);
    }
}

// ---------------------------------------------------------------------------
extern "C" void kernel_launch(void* const* d_in, const int* in_sizes, int n_in,
                              void* d_out, int out_size)
{
    const float* input = (const float*)d_in[0];
    const float* eq    = (const float*)d_in[1];
    const float* q0    = (const float*)d_in[2];
    const float* q1    = (const float*)d_in[3];
    const float* q2    = (const float*)d_in[4];
    const float* q3    = (const float*)d_in[5];
    const float* q4    = (const float*)d_in[6];
    const float* Wx1   = (const float*)d_in[7];
    const float* bx1   = (const float*)d_in[8];
    const float* Wx2   = (const float*)d_in[9];
    const float* bx2   = (const float*)d_in[10];
    const float* Wq0   = (const float*)d_in[11];
    const float* bq0   = (const float*)d_in[12];
    const float* Wq1   = (const float*)d_in[13];
    const float* bq1   = (const float*)d_in[14];
    const float* Wq2   = (const float*)d_in[15];
    const float* bq2   = (const float*)d_in[16];
    const float* Wq3   = (const float*)d_in[17];
    const float* bq3   = (const float*)d_in[18];
    const float* Wq4   = (const float*)d_in[19];
    const float* bq4   = (const float*)d_in[20];

    const int N = in_sizes[0] / 3;

    w2r_fused_kernel<<<HH / 2, 256>>>(eq, q0, q1, q2, q3, q4,
                                      Wq0, bq0, Wq1, bq1, Wq2, bq2,
                                      Wq3, bq3, Wq4, bq4, bx2, Wx2);
    main_kernel<<<GRID_MAIN, BLOCK_MAIN>>>(input, Wx1, bx1, (float*)d_out, N);
}

// round 17
// speedup vs baseline: 1.0019x; 1.0019x over previous
#include <cuda_runtime.h>
#include <cuda_fp16.h>

#define HH   256
#define P5   1024
#define NQ   128
#define GRID_MAIN  152   // GB300 SM count; 1 block/SM, all co-resident
#define BLOCK_MAIN 768   // 24 warps/SM = 6/SMSP

__device__ float    g_w2r[HH];
__device__ float    g_c;
__device__ unsigned g_bar;   // monotonic ticket counter (zero-init at load)

__device__ __forceinline__ float warp_sum(float v) {
    #pragma unroll
    for (int o = 16; o; o >>= 1) v += __shfl_xor_sync(0xffffffffu, v, o);
    return v;
}
__device__ __forceinline__ unsigned h2_to_u(__half2 h) {
    return *reinterpret_cast<unsigned*>(&h);
}
__device__ __forceinline__ __half2 u_to_h2(unsigned u) {
    return *reinterpret_cast<__half2*>(&u);
}
__device__ __forceinline__ unsigned tanh2_h2(unsigned z2) {
    unsigned t;
    asm("tanh.approx.f16x2 %0, %1;" : "=r"(t) : "r"(z2));
    return t;
}

// ---------------------------------------------------------------------------
// ONE fused persistent kernel.
// Phase A (blocks 0..127): rhs via rank-1 collapse + 2 rows of w2r = Wx2@rhs
//   (block 0 also c = bx2.rhs). All blocks meanwhile pack f16x2 weights.
// Grid ticket-barrier (replay-safe: each launch adds exactly GRID tickets;
//   launches are stream-serialized so the counter is a multiple of GRID at
//   every launch boundary).
// Phase B (all blocks): out[n] = c + sum_h tanh(z_h) * w2r[h], h in f16x2
//   pairs: 3 HFMA2 -> tanh.approx.f16x2 -> exact ALU bit-surgery unpack
//   (as_float(sign|mag<<13) == tanh * 2^-112), f32 scaled accumulate,
//   epilogue FMA applies 2^112 + c.   (R15 main loop, best measured.)
// ---------------------------------------------------------------------------
__global__ __launch_bounds__(BLOCK_MAIN)
void fused_kernel(
    const float* __restrict__ input,
    const float* __restrict__ eq,
    const float* __restrict__ q0, const float* __restrict__ q1,
    const float* __restrict__ q2, const float* __restrict__ q3,
    const float* __restrict__ q4,
    const float* __restrict__ Wx1, const float* __restrict__ bx1,
    const float* __restrict__ Wx2, const float* __restrict__ bx2,
    const float* __restrict__ Wq0, const float* __restrict__ bq0,
    const float* __restrict__ Wq1, const float* __restrict__ bq1,
    const float* __restrict__ Wq2, const float* __restrict__ bq2,
    const float* __restrict__ Wq3, const float* __restrict__ bq3,
    const float* __restrict__ Wq4, const float* __restrict__ bq4,
    float* __restrict__ out, int N)
{
    __shared__ float  s[5][64];
    __shared__ float  t01[16][16];
    __shared__ float  t23[16][16];
    __shared__ float  partA[5][4], partB[5][4];
    __shared__ float  sA[5], sB[5];
    __shared__ float  red[8];
    __shared__ uint4  sWp[HH / 2];   // {wx2,wy2,wz2,b2} half2-packed per h-pair
    __shared__ float2 sRp[HH / 2];   // {w2r[2j], w2r[2j+1]}
    __shared__ float  sC;

    const int tid  = threadIdx.x;
    const int lane = tid & 31;
    const int wrp  = tid >> 5;

    // ---- pack f16x2 weights (ALL blocks; overlaps with phase A) ----
    if (tid < HH / 2) {
        const int j = 2 * tid;
        __half2 wx2 = __floats2half2_rn(Wx1[j],          Wx1[j + 1]);
        __half2 wy2 = __floats2half2_rn(Wx1[HH + j],     Wx1[HH + j + 1]);
        __half2 wz2 = __floats2half2_rn(Wx1[2 * HH + j], Wx1[2 * HH + j + 1]);
        __half2 b2  = __floats2half2_rn(bx1[j],          bx1[j + 1]);
        uint4 w;
        w.x = h2_to_u(wx2); w.y = h2_to_u(wy2);
        w.z = h2_to_u(wz2); w.w = h2_to_u(b2);
        sWp[tid] = w;
    }

    // ---- Phase A: blocks 0..127 compute rhs + 2 w2r rows ----
    if (blockIdx.x < HH / 2 / 1) {   // 128 blocks
        if (blockIdx.x < 128) {
            const int h0 = blockIdx.x * 2;

            float4 wrow0 = make_float4(0.f, 0.f, 0.f, 0.f);
            float4 wrow1 = make_float4(0.f, 0.f, 0.f, 0.f);
            if (tid < 256) {
                wrow0 = reinterpret_cast<const float4*>(Wx2 + h0 * P5)[tid];
                wrow1 = reinterpret_cast<const float4*>(Wx2 + (h0 + 1) * P5)[tid];
            }

            const float eqv = eq[0];

            if (tid < NQ) {
                const float* qp[5] = {q0, q1, q2, q3, q4};
                #pragma unroll
                for (int i = 0; i < 5; i++) {
                    float q = qp[i][tid];
                    float y = __expf(-q * q * eqv);
                    float a = warp_sum(y * q);
                    float b = warp_sum(y);
                    if (lane == 0) { partA[i][wrp] = a; partB[i][wrp] = b; }
                }
            }
            __syncthreads();
            if (tid < 5) {
                sA[tid] = partA[tid][0] + partA[tid][1] + partA[tid][2] + partA[tid][3];
                sB[tid] = partB[tid][0] + partB[tid][1] + partB[tid][2] + partB[tid][3];
            }
            __syncthreads();

            if (tid < 64) {
                s[0][tid] = sA[0] * Wq0[tid] + sB[0] * bq0[tid];
                s[1][tid] = sA[1] * Wq1[tid] + sB[1] * bq1[tid];
                s[2][tid] = sA[2] * Wq2[tid] + sB[2] * bq2[tid];
                s[3][tid] = sA[3] * Wq3[tid] + sB[3] * bq3[tid];
                s[4][tid] = sA[4] * Wq4[tid] + sB[4] * bq4[tid];
            }
            __syncthreads();

            if (tid < 256) {
                int pq = tid >> 4;
                int x  = tid & 15;
                t01[x][pq] = s[0][(pq >> 2) * 16 + x] * s[1][(pq & 3) * 16 + x];
                t23[x][pq] = s[2][(pq >> 2) * 16 + x] * s[3][(pq & 3) * 16 + x];
            }
            __syncthreads();

            float d0 = 0.f, d1 = 0.f, cp = 0.f;
            if (tid < 256) {
                const int bd = tid >> 4;
                const int fm = tid & 15;
                float a0 = 0.f, a1 = 0.f, a2 = 0.f, a3 = 0.f;
                #pragma unroll
                for (int x = 0; x < 16; x++) {
                    float u = t01[x][bd] * t23[x][fm];
                    a0 = fmaf(u, s[4][x],      a0);
                    a1 = fmaf(u, s[4][16 + x], a1);
                    a2 = fmaf(u, s[4][32 + x], a2);
                    a3 = fmaf(u, s[4][48 + x], a3);
                }
                d0 = wrow0.x * a0 + wrow0.y * a1 + wrow0.z * a2 + wrow0.w * a3;
                d1 = wrow1.x * a0 + wrow1.y * a1 + wrow1.z * a2 + wrow1.w * a3;
                if (blockIdx.x == 0) {
                    float4 bv = reinterpret_cast<const float4*>(bx2)[tid];
                    cp = a0 * bv.x + a1 * bv.y + a2 * bv.z + a3 * bv.w;
                }
            }
            d0 = warp_sum(d0);
            d1 = warp_sum(d1);
            if (lane == 0 && wrp < 8) { red[wrp] = d0; }
            __syncthreads();
            if (tid == 0) {
                float t = 0.f;
                #pragma unroll
                for (int w = 0; w < 8; w++) t += red[w];
                g_w2r[h0] = t;
            }
            __syncthreads();
            if (lane == 0 && wrp < 8) { red[wrp] = d1; }
            __syncthreads();
            if (tid == 0) {
                float t = 0.f;
                #pragma unroll
                for (int w = 0; w < 8; w++) t += red[w];
                g_w2r[h0 + 1] = t;
            }
            if (blockIdx.x == 0) {
                cp = warp_sum(cp);
                __syncthreads();
                if (lane == 0 && wrp < 8) red[wrp] = cp;
                __syncthreads();
                if (tid == 0) {
                    float c = 0.f;
                    #pragma unroll
                    for (int w = 0; w < 8; w++) c += red[w];
                    g_c = c;
                }
            }
        }
    }
    __syncthreads();

    // ---- grid ticket barrier (replay-safe) ----
    if (tid == 0) {
        __threadfence();                        // publish g_w2r / g_c
        unsigned t = atomicAdd(&g_bar, 1u);
        unsigned target = t - (t % GRID_MAIN) + GRID_MAIN;
        while (*(volatile unsigned*)&g_bar < target) { }
        __threadfence();                        // acquire
    }
    __syncthreads();

    // ---- load w2r + c into smem ----
    if (tid < HH / 2) sRp[tid] = make_float2(g_w2r[2 * tid], g_w2r[2 * tid + 1]);
    if (tid == 0) sC = g_c;
    __syncthreads();

    // ---- Phase B: main loop (R15 pair version) ----
    const int ppb  = (N + GRID_MAIN - 1) / GRID_MAIN;   // 658 for N=100000
    const int base = blockIdx.x * ppb;
    const int end  = min(base + ppb, N);
    const float c  = sC;

    for (int n0 = base; n0 < end; n0 += BLOCK_MAIN) {
        const int  n = n0 + tid;
        const bool v = n < end;
        float x0 = 0.f, x1 = 0.f, x2 = 0.f;
        if (v) { x0 = input[3 * n]; x1 = input[3 * n + 1]; x2 = input[3 * n + 2]; }

        const __half2 x0d = __float2half2_rn(x0);
        const __half2 x1d = __float2half2_rn(x1);
        const __half2 x2d = __float2half2_rn(x2);

        float acc = 0.f;                 // scaled domain (x 2^-112)
        #pragma unroll 8
        for (int hp = 0; hp < HH / 2; hp++) {
            uint4  w  = sWp[hp];
            float2 rp = sRp[hp];

            __half2 z2 = __hfma2(x0d, u_to_h2(w.x),
                         __hfma2(x1d, u_to_h2(w.y),
                         __hfma2(x2d, u_to_h2(w.z),
                                 u_to_h2(w.w))));           // 3 HFMA2

            unsigned t = tanh2_h2(h2_to_u(z2));             // 1 XU op

            unsigned lo = ((t << 16) & 0x80000000u) | ((t & 0x7FFFu) << 13);
            unsigned hi = (t & 0x80000000u) | ((t >> 3) & 0x0FFFE000u);

            acc = fmaf(__uint_as_float(lo), rp.x, acc);
            acc = fmaf(__uint_as_float(hi), rp.y, acc);
        }
        if (v) out[n] = fmaf(acc, 0x1p+112f, c);
    }
}

// ---------------------------------------------------------------------------
extern "C" void kernel_launch(void* const* d_in, const int* in_sizes, int n_in,
                              void* d_out, int out_size)
{
    const float* input = (const float*)d_in[0];
    const float* eq    = (const float*)d_in[1];
    const float* q0    = (const float*)d_in[2];
    const float* q1    = (const float*)d_in[3];
    const float* q2    = (const float*)d_in[4];
    const float* q3    = (const float*)d_in[5];
    const float* q4    = (const float*)d_in[6];
    const float* Wx1   = (const float*)d_in[7];
    const float* bx1   = (const float*)d_in[8];
    const float* Wx2   = (const float*)d_in[9];
    const float* bx2   = (const float*)d_in[10];
    const float* Wq0   = (const float*)d_in[11];
    const float* bq0   = (const float*)d_in[12];
    const float* Wq1   = (const float*)d_in[13];
    const float* bq1   = (const float*)d_in[14];
    const float* Wq2   = (const float*)d_in[15];
    const float* bq2   = (const float*)d_in[16];
    const float* Wq3   = (const float*)d_in[17];
    const float* bq3   = (const float*)d_in[18];
    const float* Wq4   = (const float*)d_in[19];
    const float* bq4   = (const float*)d_in[20];

    const int N = in_sizes[0] / 3;

    fused_kernel<<<GRID_MAIN, BLOCK_MAIN>>>(
        input, eq, q0, q1, q2, q3, q4, Wx1, bx1, Wx2, bx2,
        Wq0, bq0, Wq1, bq1, Wq2, bq2, Wq3, bq3, Wq4, bq4,
        (float*)d_out, N);
}